// round 2
// baseline (speedup 1.0000x reference)
#include <cuda_runtime.h>
#include <math.h>

constexpr int NV = 50000, NC = 210000, NE = 630000, NG = 32, ROUNDS = 16;

__device__ float g_vars   [NV*64];
__device__ float g_clauses[NC*64];
__device__ float g_qin    [NV*68];
__device__ float g_qh     [NV*64];
__device__ float g_query  [NV*64];
__device__ float g_lits   [2*NV*64];
__device__ float g_sig    [NV*64];
__device__ float g_cl     [NC*64];
__device__ float g_cin    [NC*128];
__device__ float g_ch     [NC*128];
__device__ float g_cd     [NC*128];
__device__ float g_acc    [2*NV*64];
__device__ float g_uin    [NV*256];
__device__ float g_uh     [NV*128];
__device__ float g_uh2    [NV*128];
__device__ float g_vraw   [NV*64];
__device__ int   g_deg    [2*NV];
__device__ float g_dw     [2*NV];
__device__ float g_vdw    [NV];
__device__ int   g_gcnt   [2*NG];
__device__ float g_stat   [2*NG*64];
__device__ float g_mean   [NG*64];
__device__ float g_rsig   [NG*64];

__device__ __forceinline__ float lrelu(float x){ return x > 0.f ? x : 0.2f*x; }
__device__ __forceinline__ float sp(float x){ return fmaxf(x,0.f) + log1pf(expf(-fabsf(x))); }

__global__ void k_setup0(){
  int i = blockIdx.x*blockDim.x + threadIdx.x, s = gridDim.x*blockDim.x;
  for(int j=i;j<2*NV;j+=s) g_deg[j]=0;
  if(i<2*NG) g_gcnt[i]=0;
}
__global__ void k_count(const int* __restrict__ lit, const int* __restrict__ vg,
                        const int* __restrict__ cg){
  int i = blockIdx.x*blockDim.x + threadIdx.x, s = gridDim.x*blockDim.x;
  for(int j=i;j<NE;j+=s) atomicAdd(&g_deg[lit[j]],1);
  for(int j=i;j<NV;j+=s) atomicAdd(&g_gcnt[NG+vg[j]],1);
  for(int j=i;j<NC;j+=s) atomicAdd(&g_gcnt[cg[j]],1);
}
__global__ void k_dw(){
  int i = blockIdx.x*blockDim.x + threadIdx.x;
  if(i<2*NV) g_dw[i] = rsqrtf(fmaxf((float)g_deg[i],1.f));
  if(i<NV)   g_vdw[i] = 4.f*rsqrtf(fmaxf((float)(g_deg[i]+g_deg[NV+i]),1.f));
}
__global__ void k_init1(){
  int i = blockIdx.x*blockDim.x + threadIdx.x, s = gridDim.x*blockDim.x;
  for(int j=i;j<NV*64;j+=s) g_vars[j]=1.f;
  for(int j=i;j<NC*64;j+=s) g_clauses[j]=1.f;
}
__global__ void k_zerof(float* __restrict__ p, int n){
  int i = blockIdx.x*blockDim.x + threadIdx.x;
  if(i<n) p[i]=0.f;
}

template<int K,int N,bool LEAKY>
__global__ void __launch_bounds__(256) k_gemm(const float* __restrict__ A,
    const float* __restrict__ W, const float* __restrict__ b,
    float* __restrict__ C, int M){
  constexpr int TN = N/16;
  __shared__ float sA[64*65];
  __shared__ float sW[64*N];
  int tid = threadIdx.x;
  int tx = tid & 15, ty = tid >> 4;
  int base = blockIdx.x * 64;
  float acc[4][TN];
  #pragma unroll
  for(int r=0;r<4;r++)
    #pragma unroll
    for(int j=0;j<TN;j++) acc[r][j] = b[tx*TN+j];
  for(int k0=0;k0<K;k0+=64){
    int kc = (K-k0 < 64) ? (K-k0) : 64;
    __syncthreads();
    for(int i=tid;i<kc*N;i+=256) sW[i] = W[(size_t)(k0 + i/N)*N + (i%N)];
    for(int i=tid;i<64*kc;i+=256){
      int r = i/kc, k = i%kc; int row = base + r;
      sA[r*65+k] = (row < M) ? A[(size_t)row*K + k0 + k] : 0.f;
    }
    __syncthreads();
    #pragma unroll 4
    for(int k=0;k<kc;k++){
      float a0 = sA[(ty*4+0)*65+k];
      float a1 = sA[(ty*4+1)*65+k];
      float a2 = sA[(ty*4+2)*65+k];
      float a3 = sA[(ty*4+3)*65+k];
      #pragma unroll
      for(int j=0;j<TN;j++){
        float w = sW[k*N + tx*TN + j];
        acc[0][j] += a0*w; acc[1][j] += a1*w;
        acc[2][j] += a2*w; acc[3][j] += a3*w;
      }
    }
  }
  #pragma unroll
  for(int r=0;r<4;r++){
    int row = base + ty*4 + r;
    if(row < M){
      #pragma unroll
      for(int j=0;j<TN;j++){
        float v = acc[r][j];
        if(LEAKY) v = lrelu(v);
        C[(size_t)row*N + tx*TN + j] = v;
      }
    }
  }
}

__global__ void k_qin(const float* __restrict__ nz){
  int i = blockIdx.x*blockDim.x + threadIdx.x;
  if(i >= NV*68) return;
  int v = i/68, c = i%68;
  g_qin[i] = (c < 64) ? g_vars[v*64+c] : nz[v*4 + (c-64)];
}
__global__ void k_lits(){
  int i = blockIdx.x*blockDim.x + threadIdx.x;
  if(i >= NV*64) return;
  float q = g_query[i];
  g_lits[i]         = sp(q);
  g_lits[NV*64 + i] = sp(-q);
  g_sig[i]          = 1.f/(1.f + expf(-q));
}
__global__ void k_cl(const int* __restrict__ lit){
  int idx = blockIdx.x*blockDim.x + threadIdx.x;
  if(idx >= NC*16) return;
  int c = idx >> 4, q = (idx & 15) * 4;
  int e = 3*c;
  int l0 = lit[e], l1 = lit[e+1], l2 = lit[e+2];
  float4 A = *(const float4*)&g_lits[(size_t)l0*64 + q];
  float4 B = *(const float4*)&g_lits[(size_t)l1*64 + q];
  float4 C = *(const float4*)&g_lits[(size_t)l2*64 + q];
  float4 o;
  o.x = expf(-(A.x+B.x+C.x)); o.y = expf(-(A.y+B.y+C.y));
  o.z = expf(-(A.z+B.z+C.z)); o.w = expf(-(A.w+B.w+C.w));
  *(float4*)&g_cl[(size_t)c*64 + q] = o;
}
__global__ void k_scatter(const int* __restrict__ lit, const float* __restrict__ src,
                          int S, int off){
  int idx = blockIdx.x*blockDim.x + threadIdx.x;
  if(idx >= NC*64) return;
  int c = idx >> 6, f = idx & 63;
  float v = src[(size_t)c*S + off + f];
  int e = 3*c;
  atomicAdd(&g_acc[(size_t)lit[e  ]*64 + f], v);
  atomicAdd(&g_acc[(size_t)lit[e+1]*64 + f], v);
  atomicAdd(&g_acc[(size_t)lit[e+2]*64 + f], v);
}
__global__ void k_vgrad(){
  int i = blockIdx.x*blockDim.x + threadIdx.x;
  if(i >= NV*64) return;
  int v = i >> 6, f = i & 63;
  float sg = g_sig[i];
  float gr = (-sg * g_acc[i] + (1.f - sg) * g_acc[NV*64 + i]) * g_vdw[v];
  g_uin[(size_t)v*256 + f]      = gr;
  g_uin[(size_t)v*256 + 64 + f] = g_vars[i];
}
__global__ void k_cin(){
  int i = blockIdx.x*blockDim.x + threadIdx.x;
  if(i >= NC*128) return;
  int c = i >> 7, f = i & 127;
  g_cin[i] = (f < 64) ? g_clauses[(size_t)c*64 + f] : 4.f * g_cl[(size_t)c*64 + (f-64)];
}
__global__ void k_vloss(){
  int i = blockIdx.x*blockDim.x + threadIdx.x;
  if(i >= 2*NV*64) return;
  int l = i >> 6, f = i & 63;
  float v = g_acc[i] * g_dw[l];
  if(l < NV) g_uin[(size_t)l*256 + 128 + f] = v;
  else       g_uin[(size_t)(l-NV)*256 + 192 + f] = v;
}

__global__ void k_stats(const float* __restrict__ src, int S, int off,
                        const int* __restrict__ gid, int n){
  __shared__ float s1[256], s2[256];
  int tid = threadIdx.x;
  int f = tid & 63, lane = tid >> 6;
  int row0 = blockIdx.x * 64;
  int rend = min(row0 + 64, n);
  int g0 = gid[row0], g1 = gid[rend-1];
  if(g0 == g1){
    float s = 0.f, q = 0.f;
    for(int r = row0 + lane; r < rend; r += 4){
      float x = src[(size_t)r*S + off + f];
      s += x; q += x*x;
    }
    s1[tid] = s; s2[tid] = q;
    __syncthreads();
    if(lane == 0){
      s = s1[f] + s1[64+f] + s1[128+f] + s1[192+f];
      q = s2[f] + s2[64+f] + s2[128+f] + s2[192+f];
      atomicAdd(&g_stat[g0*64 + f], s);
      atomicAdd(&g_stat[NG*64 + g0*64 + f], q);
    }
  } else {
    for(int r = row0 + lane; r < rend; r += 4){
      float x = src[(size_t)r*S + off + f];
      int g = gid[r];
      atomicAdd(&g_stat[g*64 + f], x);
      atomicAdd(&g_stat[NG*64 + g*64 + f], x*x);
    }
  }
}
__global__ void k_fin(int cntoff){
  int i = blockIdx.x*blockDim.x + threadIdx.x;
  if(i >= NG*64) return;
  int g = i >> 6;
  float inv = 1.f / fmaxf((float)g_gcnt[cntoff + g], 1.f);
  float m = g_stat[i] * inv;
  float var = g_stat[NG*64 + i] * inv - m*m;
  g_mean[i] = m;
  g_rsig[i] = rsqrtf(fmaxf(var, 0.f) + 1e-6f);
}
__global__ void k_apply(const float* __restrict__ src, int S, int off,
                        float* __restrict__ target, const int* __restrict__ gid, int n){
  int i = blockIdx.x*blockDim.x + threadIdx.x;
  if(i >= n*64) return;
  int r = i >> 6, f = i & 63;
  int g = gid[r];
  float x = src[(size_t)r*S + off + f];
  float y = (x - g_mean[g*64+f]) * g_rsig[g*64+f] * 0.25f;
  target[i] = y + 0.1f * target[i];
}

__global__ void k_logits(const float* __restrict__ oW1, const float* __restrict__ ob1,
                         float* __restrict__ out){
  int wid = (blockIdx.x*blockDim.x + threadIdx.x) >> 5;
  int lane = threadIdx.x & 31;
  if(wid >= NC) return;
  float v = g_ch[(size_t)wid*64 + lane]      * oW1[lane]
          + g_ch[(size_t)wid*64 + 32 + lane] * oW1[32 + lane];
  #pragma unroll
  for(int o=16;o>0;o>>=1) v += __shfl_down_sync(0xffffffffu, v, o);
  if(lane == 0){
    float logit = v + ob1[0];
    out[wid]      = 1.f/(1.f + expf(-logit));
    out[NC + wid] = sp(logit);
  }
}

static float* fsym(const void* s){ void* p=nullptr; cudaGetSymbolAddress(&p, s); return (float*)p; }

extern "C" void kernel_launch(void* const* d_in, const int* in_sizes, int n_in,
                              void* d_out, int out_size){
  const int*   lit   = (const int*)d_in[0];
  const int*   vg    = (const int*)d_in[2];
  const int*   cg    = (const int*)d_in[3];
  const float* noise = (const float*)d_in[4];
  const float *qW0=(const float*)d_in[5],  *qb0=(const float*)d_in[6];
  const float *qW1=(const float*)d_in[7],  *qb1=(const float*)d_in[8];
  const float *cW0=(const float*)d_in[9],  *cb0=(const float*)d_in[10];
  const float *cW1=(const float*)d_in[11], *cb1=(const float*)d_in[12];
  const float *uW0=(const float*)d_in[13], *ub0=(const float*)d_in[14];
  const float *uW1=(const float*)d_in[15], *ub1=(const float*)d_in[16];
  const float *uW2=(const float*)d_in[17], *ub2=(const float*)d_in[18];
  const float *oW0=(const float*)d_in[19], *ob0=(const float*)d_in[20];
  const float *oW1=(const float*)d_in[21], *ob1=(const float*)d_in[22];
  float* out = (float*)d_out;

  float *p_qin  = fsym(g_qin),  *p_qh  = fsym(g_qh),  *p_query = fsym(g_query);
  float *p_cin  = fsym(g_cin),  *p_ch  = fsym(g_ch),  *p_cd    = fsym(g_cd);
  float *p_uin  = fsym(g_uin),  *p_uh  = fsym(g_uh),  *p_uh2   = fsym(g_uh2);
  float *p_vraw = fsym(g_vraw), *p_vars= fsym(g_vars);
  float *p_claus= fsym(g_clauses);
  float *p_acc  = fsym(g_acc),  *p_stat= fsym(g_stat), *p_cl   = fsym(g_cl);

  const int T = 256;
  auto B = [](long n){ return (int)((n + 255) / 256); };
  int gbV = (NV + 63) / 64, gbC = (NC + 63) / 64;

  k_setup0<<<256, T>>>();
  k_count<<<1024, T>>>(lit, vg, cg);
  k_dw<<<B(2L*NV), T>>>();
  k_init1<<<4096, T>>>();

  for(int t = 0; t < ROUNDS; t++){
    const float* nz = noise + (size_t)t * NV * 4;
    k_qin<<<B((long)NV*68), T>>>(nz);
    k_gemm<68,64,true ><<<gbV, T>>>(p_qin, qW0, qb0, p_qh, NV);
    k_gemm<64,64,false><<<gbV, T>>>(p_qh,  qW1, qb1, p_query, NV);
    k_lits<<<B((long)NV*64), T>>>();
    k_cl<<<B((long)NC*16), T>>>(lit);

    k_zerof<<<B(2L*NV*64), T>>>(p_acc, 2*NV*64);
    k_scatter<<<B((long)NC*64), T>>>(lit, p_cl, 64, 0);
    k_vgrad<<<B((long)NV*64), T>>>();

    k_cin<<<B((long)NC*128), T>>>();
    k_gemm<128,128,true ><<<gbC, T>>>(p_cin, cW0, cb0, p_ch, NC);
    k_gemm<128,128,false><<<gbC, T>>>(p_ch,  cW1, cb1, p_cd, NC);

    k_zerof<<<B(2L*NG*64), T>>>(p_stat, 2*NG*64);
    k_stats<<<gbC, T>>>(p_cd, 128, 64, cg, NC);
    k_fin<<<8, T>>>(0);
    k_apply<<<B((long)NC*64), T>>>(p_cd, 128, 64, p_claus, cg, NC);

    k_zerof<<<B(2L*NV*64), T>>>(p_acc, 2*NV*64);
    k_scatter<<<B((long)NC*64), T>>>(lit, p_cd, 128, 0);
    k_vloss<<<B(2L*NV*64), T>>>();

    k_gemm<256,128,true ><<<gbV, T>>>(p_uin, uW0, ub0, p_uh, NV);
    k_gemm<128,128,true ><<<gbV, T>>>(p_uh,  uW1, ub1, p_uh2, NV);
    k_gemm<128,64,false ><<<gbV, T>>>(p_uh2, uW2, ub2, p_vraw, NV);

    k_zerof<<<B(2L*NG*64), T>>>(p_stat, 2*NG*64);
    k_stats<<<gbV, T>>>(p_vraw, 64, 0, vg, NV);
    k_fin<<<8, T>>>(NG);
    k_apply<<<B((long)NV*64), T>>>(p_vraw, 64, 0, p_vars, vg, NV);
  }

  k_gemm<64,64,true><<<gbC, T>>>(p_claus, oW0, ob0, p_ch, NC);
  k_logits<<<B((long)NC*32), T>>>(oW1, ob1, out);

  (void)in_sizes; (void)n_in; (void)out_size;
}

// round 3
// speedup vs baseline: 1.2670x; 1.2670x over previous
#include <cuda_runtime.h>
#include <math.h>

constexpr int NV = 50000, NC = 210000, NE = 630000, NG = 32, ROUNDS = 16;

// ----------------- device scratch -----------------
__device__ float g_vars   [NV*64];
__device__ float g_clauses[NC*64];
__device__ float g_qh     [NV*64];
__device__ float g_lits   [2*NV*64];
__device__ float g_sig    [NV*64];
__device__ float g_cl     [NC*64];
__device__ float g_ch     [NC*128];
__device__ float g_cd     [NC*128];
__device__ float g_uin    [NV*256];
__device__ float g_uh     [NV*128];
__device__ float g_uh2    [NV*128];
__device__ float g_vraw   [NV*64];
__device__ int   g_deg    [2*NV];
__device__ int   g_off    [2*NV+1];
__device__ int   g_cur    [2*NV];
__device__ int   g_pcl    [NE];      // clause id per CSR slot
__device__ float g_dw     [2*NV];
__device__ float g_vdw    [NV];
__device__ int   g_gcnt   [2*NG];
__device__ float g_stat   [2*NG*64];
__device__ float g_mean   [NG*64];
__device__ float g_rsig   [NG*64];

__device__ __forceinline__ float lrelu(float x){ return x > 0.f ? x : 0.2f*x; }
__device__ __forceinline__ float sp(float x){ return fmaxf(x,0.f) + log1pf(expf(-fabsf(x))); }

// ----------------- setup -----------------
__global__ void k_setup0(){
  int i = blockIdx.x*blockDim.x + threadIdx.x, s = gridDim.x*blockDim.x;
  for(int j=i;j<2*NV;j+=s) g_deg[j]=0;
  if(i<2*NG) g_gcnt[i]=0;
}
__global__ void k_count(const int* __restrict__ lit, const int* __restrict__ vg,
                        const int* __restrict__ cg){
  int i = blockIdx.x*blockDim.x + threadIdx.x, s = gridDim.x*blockDim.x;
  for(int j=i;j<NE;j+=s) atomicAdd(&g_deg[lit[j]],1);
  for(int j=i;j<NV;j+=s) atomicAdd(&g_gcnt[NG+vg[j]],1);
  for(int j=i;j<NC;j+=s) atomicAdd(&g_gcnt[cg[j]],1);
}
__global__ void k_scan(){
  __shared__ int sh[1024];
  __shared__ int carry;
  int tid = threadIdx.x;
  if(tid==0) carry=0;
  __syncthreads();
  for(int base=0; base<2*NV; base+=1024){
    int i = base + tid;
    int v = (i < 2*NV) ? g_deg[i] : 0;
    sh[tid] = v; __syncthreads();
    for(int d=1; d<1024; d<<=1){
      int t = (tid>=d) ? sh[tid-d] : 0;
      __syncthreads();
      sh[tid] += t;
      __syncthreads();
    }
    int excl = sh[tid] - v;
    int total = sh[1023];
    int c = carry;
    if(i < 2*NV){ g_off[i] = c + excl; g_cur[i] = c + excl; }
    __syncthreads();
    if(tid==0) carry = c + total;
    __syncthreads();
  }
  if(tid==0) g_off[2*NV] = carry;
}
__global__ void k_fill(const int* __restrict__ lit){
  int i = blockIdx.x*blockDim.x + threadIdx.x, s = gridDim.x*blockDim.x;
  for(int e=i;e<NE;e+=s){
    int l = lit[e];
    int p = atomicAdd(&g_cur[l],1);
    g_pcl[p] = e/3;
  }
}
__global__ void k_dw(){
  int i = blockIdx.x*blockDim.x + threadIdx.x;
  if(i<2*NV) g_dw[i] = rsqrtf(fmaxf((float)g_deg[i],1.f));
  if(i<NV)   g_vdw[i] = 4.f*rsqrtf(fmaxf((float)(g_deg[i]+g_deg[NV+i]),1.f));
}
__global__ void k_init1(){
  int i = blockIdx.x*blockDim.x + threadIdx.x, s = gridDim.x*blockDim.x;
  for(int j=i;j<NV*64;j+=s) g_vars[j]=1.f;
  for(int j=i;j<NC*64;j+=s) g_clauses[j]=1.f;
}
__global__ void k_zerof(float* __restrict__ p, int n){
  int i = blockIdx.x*blockDim.x + threadIdx.x;
  if(i<n) p[i]=0.f;
}

// ----------------- fused MLP layer -----------------
// C[M,N] = act(concat(A0[:,0:K0], s1*A1[:,0:K1]) @ W + b)
// ACT: 0=none, 1=leaky, 2=lits epilogue (writes g_lits/g_sig), 3=output head
template<int K0,int K1,int N,int ACT>
__global__ void __launch_bounds__(256) k_mlp(
    const float* __restrict__ A0, const float* __restrict__ A1, float s1,
    const float* __restrict__ W, const float* __restrict__ b,
    float* __restrict__ C, int M,
    const float* __restrict__ w2, const float* __restrict__ b2){
  constexpr int K = K0 + K1;
  constexpr int TN = N/16;
  __shared__ float sAT[64*64];
  __shared__ float sW[64*N];
  int tid = threadIdx.x;
  int tx = tid & 15, ty = tid >> 4;
  int base = blockIdx.x * 64;
  int c0 = tx*TN, r0 = ty*4;
  float acc[4][TN];
  #pragma unroll
  for(int j=0;j<TN;j++){
    float bv = b[c0+j];
    #pragma unroll
    for(int r=0;r<4;r++) acc[r][j] = bv;
  }
  for(int k0=0;k0<K;k0+=64){
    int kc = (K-k0 < 64) ? (K-k0) : 64;
    __syncthreads();
    // W chunk: contiguous rows -> straight float4 copy
    {
      const float4* Wsrc = (const float4*)(W + (size_t)k0*N);
      float4* Wdst = (float4*)sW;
      for(int i=tid;i<kc*N/4;i+=256) Wdst[i] = Wsrc[i];
    }
    // A chunk, transposed into sAT[k][row]
    {
      int nq = kc >> 2;
      for(int i=tid;i<64*nq;i+=256){
        int r = i & 63, kq = i >> 6;
        int col = k0 + kq*4;
        int row = base + r;
        float4 v = make_float4(0.f,0.f,0.f,0.f);
        if(row < M){
          if(col < K0) v = *(const float4*)&A0[(size_t)row*K0 + col];
          else {
            v = *(const float4*)&A1[(size_t)row*K1 + (col-K0)];
            v.x*=s1; v.y*=s1; v.z*=s1; v.w*=s1;
          }
        }
        int kk = kq*4;
        sAT[(kk+0)*64+r]=v.x; sAT[(kk+1)*64+r]=v.y;
        sAT[(kk+2)*64+r]=v.z; sAT[(kk+3)*64+r]=v.w;
      }
    }
    __syncthreads();
    #pragma unroll 4
    for(int k=0;k<kc;k++){
      float4 a = *(const float4*)&sAT[k*64 + r0];
      float wv[TN];
      #pragma unroll
      for(int j0=0;j0<TN;j0+=4){
        float4 w = *(const float4*)&sW[k*N + c0 + j0];
        wv[j0]=w.x; wv[j0+1]=w.y; wv[j0+2]=w.z; wv[j0+3]=w.w;
      }
      float ar[4] = {a.x, a.y, a.z, a.w};
      #pragma unroll
      for(int r=0;r<4;r++)
        #pragma unroll
        for(int j=0;j<TN;j++) acc[r][j] += ar[r]*wv[j];
    }
  }
  if(ACT==0 || ACT==1){
    #pragma unroll
    for(int r=0;r<4;r++){
      int row = base + r0 + r;
      if(row < M){
        #pragma unroll
        for(int j0=0;j0<TN;j0+=4){
          float4 o;
          o.x = (ACT==1)? lrelu(acc[r][j0  ]) : acc[r][j0  ];
          o.y = (ACT==1)? lrelu(acc[r][j0+1]) : acc[r][j0+1];
          o.z = (ACT==1)? lrelu(acc[r][j0+2]) : acc[r][j0+2];
          o.w = (ACT==1)? lrelu(acc[r][j0+3]) : acc[r][j0+3];
          *(float4*)&C[(size_t)row*N + c0 + j0] = o;
        }
      }
    }
  } else if(ACT==2){
    // N==64, TN==4: q -> softplus(q), softplus(-q), sigmoid(q)
    #pragma unroll
    for(int r=0;r<4;r++){
      int row = base + r0 + r;
      if(row < M){
        float4 lp, ln, sg;
        lp.x = sp( acc[r][0]); lp.y = sp( acc[r][1]); lp.z = sp( acc[r][2]); lp.w = sp( acc[r][3]);
        ln.x = sp(-acc[r][0]); ln.y = sp(-acc[r][1]); ln.z = sp(-acc[r][2]); ln.w = sp(-acc[r][3]);
        sg.x = 1.f/(1.f+expf(-acc[r][0])); sg.y = 1.f/(1.f+expf(-acc[r][1]));
        sg.z = 1.f/(1.f+expf(-acc[r][2])); sg.w = 1.f/(1.f+expf(-acc[r][3]));
        *(float4*)&g_lits[(size_t)row*64 + c0]        = lp;
        *(float4*)&g_lits[(size_t)(NV+row)*64 + c0]   = ln;
        *(float4*)&g_sig [(size_t)row*64 + c0]        = sg;
      }
    }
  } else { // ACT==3: logits head, N==64, TN==4
    float p[4];
    #pragma unroll
    for(int r=0;r<4;r++){
      float s = 0.f;
      #pragma unroll
      for(int j=0;j<TN;j++) s += lrelu(acc[r][j]) * w2[c0+j];
      p[r] = s;
    }
    #pragma unroll
    for(int r=0;r<4;r++){
      #pragma unroll
      for(int o=8;o>0;o>>=1) p[r] += __shfl_down_sync(0xffffffffu, p[r], o, 16);
    }
    if(tx==0){
      float bb = b2[0];
      #pragma unroll
      for(int r=0;r<4;r++){
        int row = base + r0 + r;
        if(row < M){
          float logit = p[r] + bb;
          C[row]      = 1.f/(1.f+expf(-logit));
          C[NC + row] = sp(logit);
        }
      }
    }
  }
}

// ----------------- per-round graph kernels -----------------
__global__ void k_cl(const int* __restrict__ lit){
  int idx = blockIdx.x*blockDim.x + threadIdx.x;
  if(idx >= NC*16) return;
  int c = idx >> 4, q = (idx & 15) * 4;
  int e = 3*c;
  int l0 = lit[e], l1 = lit[e+1], l2 = lit[e+2];
  float4 A = *(const float4*)&g_lits[(size_t)l0*64 + q];
  float4 B = *(const float4*)&g_lits[(size_t)l1*64 + q];
  float4 C = *(const float4*)&g_lits[(size_t)l2*64 + q];
  float4 o;
  o.x = expf(-(A.x+B.x+C.x)); o.y = expf(-(A.y+B.y+C.y));
  o.z = expf(-(A.z+B.z+C.z)); o.w = expf(-(A.w+B.w+C.w));
  *(float4*)&g_cl[(size_t)c*64 + q] = o;
}

// fused: vgrad (analytic), vars copy, variables_loss gathers -> g_uin
__global__ void __launch_bounds__(256) k_uin(){
  int tid = threadIdx.x;
  int f = tid & 63;
  int v = blockIdx.x*4 + (tid >> 6);
  if(v >= NV) return;
  int p0 = g_off[v],    p1 = g_off[v+1];
  int n0 = g_off[NV+v], n1 = g_off[NV+v+1];
  float scl=0.f, scd=0.f, ncl=0.f, ncd=0.f;
  for(int e=p0;e<p1;e++){
    int c = g_pcl[e];
    scl += g_cl[(size_t)c*64 + f];
    scd += g_cd[(size_t)c*128 + f];
  }
  for(int e=n0;e<n1;e++){
    int c = g_pcl[e];
    ncl += g_cl[(size_t)c*64 + f];
    ncd += g_cd[(size_t)c*128 + f];
  }
  float sg = g_sig[(size_t)v*64 + f];
  float gr = (-sg*scl + (1.f-sg)*ncl) * g_vdw[v];
  size_t o = (size_t)v*256;
  g_uin[o + f]       = gr;
  g_uin[o + 64 + f]  = g_vars[(size_t)v*64 + f];
  g_uin[o + 128 + f] = scd * g_dw[v];
  g_uin[o + 192 + f] = ncd * g_dw[NV+v];
}

// ----------------- pair-norm -----------------
__global__ void k_stats(const float* __restrict__ src, int S, int off,
                        const int* __restrict__ gid, int n){
  __shared__ float s1[256], s2[256];
  int tid = threadIdx.x;
  int f = tid & 63, lane = tid >> 6;
  int row0 = blockIdx.x * 64;
  int rend = min(row0 + 64, n);
  int g0 = gid[row0], g1 = gid[rend-1];
  if(g0 == g1){
    float s = 0.f, q = 0.f;
    for(int r = row0 + lane; r < rend; r += 4){
      float x = src[(size_t)r*S + off + f];
      s += x; q += x*x;
    }
    s1[tid] = s; s2[tid] = q;
    __syncthreads();
    if(lane == 0){
      s = s1[f] + s1[64+f] + s1[128+f] + s1[192+f];
      q = s2[f] + s2[64+f] + s2[128+f] + s2[192+f];
      atomicAdd(&g_stat[g0*64 + f], s);
      atomicAdd(&g_stat[NG*64 + g0*64 + f], q);
    }
  } else {
    for(int r = row0 + lane; r < rend; r += 4){
      float x = src[(size_t)r*S + off + f];
      int g = gid[r];
      atomicAdd(&g_stat[g*64 + f], x);
      atomicAdd(&g_stat[NG*64 + g*64 + f], x*x);
    }
  }
}
__global__ void k_fin(int cntoff){
  int i = blockIdx.x*blockDim.x + threadIdx.x;
  if(i >= NG*64) return;
  int g = i >> 6;
  float inv = 1.f / fmaxf((float)g_gcnt[cntoff + g], 1.f);
  float m = g_stat[i] * inv;
  float var = g_stat[NG*64 + i] * inv - m*m;
  g_mean[i] = m;
  g_rsig[i] = rsqrtf(fmaxf(var, 0.f) + 1e-6f);
}
__global__ void k_apply(const float* __restrict__ src, int S, int off,
                        float* __restrict__ target, const int* __restrict__ gid, int n){
  int i = blockIdx.x*blockDim.x + threadIdx.x;
  if(i >= n*64) return;
  int r = i >> 6, f = i & 63;
  int g = gid[r];
  float x = src[(size_t)r*S + off + f];
  float y = (x - g_mean[g*64+f]) * g_rsig[g*64+f] * 0.25f;
  target[i] = y + 0.1f * target[i];
}

// ----------------- host -----------------
static float* fsym(const void* s){ void* p=nullptr; cudaGetSymbolAddress(&p, s); return (float*)p; }

extern "C" void kernel_launch(void* const* d_in, const int* in_sizes, int n_in,
                              void* d_out, int out_size){
  const int*   lit   = (const int*)d_in[0];
  const int*   vg    = (const int*)d_in[2];
  const int*   cg    = (const int*)d_in[3];
  const float* noise = (const float*)d_in[4];
  const float *qW0=(const float*)d_in[5],  *qb0=(const float*)d_in[6];
  const float *qW1=(const float*)d_in[7],  *qb1=(const float*)d_in[8];
  const float *cW0=(const float*)d_in[9],  *cb0=(const float*)d_in[10];
  const float *cW1=(const float*)d_in[11], *cb1=(const float*)d_in[12];
  const float *uW0=(const float*)d_in[13], *ub0=(const float*)d_in[14];
  const float *uW1=(const float*)d_in[15], *ub1=(const float*)d_in[16];
  const float *uW2=(const float*)d_in[17], *ub2=(const float*)d_in[18];
  const float *oW0=(const float*)d_in[19], *ob0=(const float*)d_in[20];
  const float *oW1=(const float*)d_in[21], *ob1=(const float*)d_in[22];
  float* out = (float*)d_out;

  float *p_qh   = fsym(g_qh);
  float *p_ch   = fsym(g_ch),  *p_cd   = fsym(g_cd),  *p_cl = fsym(g_cl);
  float *p_uin  = fsym(g_uin), *p_uh   = fsym(g_uh),  *p_uh2 = fsym(g_uh2);
  float *p_vraw = fsym(g_vraw),*p_vars = fsym(g_vars);
  float *p_claus= fsym(g_clauses);
  float *p_stat = fsym(g_stat);

  const int T = 256;
  auto B = [](long n){ return (int)((n + 255) / 256); };
  int gbV = (NV + 63) / 64, gbC = (NC + 63) / 64;

  k_setup0<<<256, T>>>();
  k_count<<<1024, T>>>(lit, vg, cg);
  k_scan<<<1, 1024>>>();
  k_fill<<<1024, T>>>(lit);
  k_dw<<<B(2L*NV), T>>>();
  k_init1<<<4096, T>>>();

  for(int t = 0; t < ROUNDS; t++){
    const float* nz = noise + (size_t)t * NV * 4;
    // query MLP (input concat fused) + literal activations (epilogue fused)
    k_mlp<64,4,64,1><<<gbV, T>>>(p_vars, nz, 1.f, qW0, qb0, p_qh, NV, nullptr, nullptr);
    k_mlp<64,0,64,2><<<gbV, T>>>(p_qh, nullptr, 0.f, qW1, qb1, nullptr, NV, nullptr, nullptr);
    k_cl<<<B((long)NC*16), T>>>(lit);

    // clause MLP (concat [clauses | 4*cl] fused)
    k_mlp<64,64,128,1><<<gbC, T>>>(p_claus, p_cl, 4.f, cW0, cb0, p_ch, NC, nullptr, nullptr);
    k_mlp<128,0,128,0><<<gbC, T>>>(p_ch, nullptr, 0.f, cW1, cb1, p_cd, NC, nullptr, nullptr);

    // clause pair-norm + state update
    k_zerof<<<B(2L*NG*64), T>>>(p_stat, 2*NG*64);
    k_stats<<<gbC, T>>>(p_cd, 128, 64, cg, NC);
    k_fin<<<8, T>>>(0);
    k_apply<<<B((long)NC*64), T>>>(p_cd, 128, 64, p_claus, cg, NC);

    // fused gather: vgrad + vars + variables_loss -> uin
    k_uin<<<(NV+3)/4, T>>>();

    // update MLP
    k_mlp<256,0,128,1><<<gbV, T>>>(p_uin, nullptr, 0.f, uW0, ub0, p_uh, NV, nullptr, nullptr);
    k_mlp<128,0,128,1><<<gbV, T>>>(p_uh,  nullptr, 0.f, uW1, ub1, p_uh2, NV, nullptr, nullptr);
    k_mlp<128,0,64,0 ><<<gbV, T>>>(p_uh2, nullptr, 0.f, uW2, ub2, p_vraw, NV, nullptr, nullptr);

    // variable pair-norm + state update
    k_zerof<<<B(2L*NG*64), T>>>(p_stat, 2*NG*64);
    k_stats<<<gbV, T>>>(p_vraw, 64, 0, vg, NV);
    k_fin<<<8, T>>>(NG);
    k_apply<<<B((long)NV*64), T>>>(p_vraw, 64, 0, p_vars, vg, NV);
  }

  // output head: logits fused (leaky(clauses@oW0+ob0)@oW1+ob1 -> sigmoid/softplus)
  k_mlp<64,0,64,3><<<gbC, T>>>(p_claus, nullptr, 0.f, oW0, ob0, out, NC, oW1, ob1);

  (void)in_sizes; (void)n_in; (void)out_size;
}